// round 11
// baseline (speedup 1.0000x reference)
#include <cuda_runtime.h>
#include <cuda_fp16.h>

// out[r,:] = FWHT_8192(scatter(u[r,:], idx)) / sqrt(8192)
//
// idx is row-invariant and SORTED -> invert the scatter into an owner-gather:
// a precompute kernel binary-searches, per thread t, the k-range whose idx
// lands in [32t, 32t+32). Each thread zeroes+fills only its OWN 16 half2
// cells (no atomics, no pre-R1 barrier).
//
// Phase layout (13 commuting H2 stages):
//   A: bits 4:0  (bit0 = f32x2 lane, bits 4:1 = reg index)   thread owns 12:5
//   B: bits 8:5  (bit0 passenger/lane)                        thread owns {12:9,4:1}
//   C: bits 12:9 (bit0 passenger/lane)                        thread owns {8:1}
// Both transposes pack half2 along bit0 and map pair-id p (bits 12:1) to cell
//   c = p ^ ((p>>4) & 31)
// which is conflict-free for every LDS/STS pattern used. W3 reuses zb (free
// after R1) so only 2 __syncthreads per row. Epilogue = 16 x STG.64.

#define D_DIM 8192
#define K_DIM 1024
#define NT    256
#define SCALE_F 0.0110485434560398047f  // 1/sqrt(8192)

__device__ int g_bounds[NT + 1];

__global__ void precompute_bounds(const int* __restrict__ idx)
{
    int t = threadIdx.x;
    if (t > NT) return;
    int target = t << 5;
    int lo = 0, hi = K_DIM;
    while (lo < hi) {                       // lower_bound(idx, target)
        int mid = (lo + hi) >> 1;
        if (idx[mid] < target) lo = mid + 1; else hi = mid;
    }
    g_bounds[t] = lo;
}

__device__ __forceinline__ float2 fadd2(float2 a, float2 b) {
    float2 c;
    asm("add.rn.f32x2 %0, %1, %2;"
        : "=l"(reinterpret_cast<unsigned long long &>(c))
        : "l"(reinterpret_cast<const unsigned long long &>(a)),
          "l"(reinterpret_cast<const unsigned long long &>(b)));
    return c;
}
__device__ __forceinline__ float2 ffma2(float2 a, float2 b, float2 c) {
    float2 d;
    asm("fma.rn.f32x2 %0, %1, %2, %3;"
        : "=l"(reinterpret_cast<unsigned long long &>(d))
        : "l"(reinterpret_cast<const unsigned long long &>(a)),
          "l"(reinterpret_cast<const unsigned long long &>(b)),
          "l"(reinterpret_cast<const unsigned long long &>(c)));
    return d;
}

__global__ __launch_bounds__(NT, 6)
void fwht_up_kernel(const float* __restrict__ u,
                    const int*   __restrict__ idx,
                    float*       __restrict__ out)
{
    __shared__ __align__(16) __half2 zb[4096];   // phase-A input / T2 buffer
    __shared__ __align__(16) __half2 tb[4096];   // T1 buffer

    const int t   = threadIdx.x;                 // 8 bits
    const int row = blockIdx.x;
    const float2 NEG1 = make_float2(-1.f, -1.f);

    // thread-const addresses
    const int obase  = (t << 4) ^ (t & 31);                          // A-side cells
    const int rbase2 = (((t >> 4) << 8) | (t & 15)) ^ (((t >> 4) & 1) << 4); // B-side
    const int r3base = t ^ ((t >> 4) & 15);                          // C-side reads

    // ---- zero own 16 cells (8 x 64-bit stores, conflict-free) ----
    {
        const int pb = obase & ~1;
#pragma unroll
        for (int k2 = 0; k2 < 8; k2++)
            *reinterpret_cast<float2*>(&zb[pb ^ (k2 << 1)]) = make_float2(0.f, 0.f);
    }

    // ---- owner-gather fill: k in [lo,hi) all land in this thread's cells ----
    {
        const int lo = g_bounds[t];
        const int hi = g_bounds[t + 1];
        const float* urow = u + (size_t)row * K_DIM;
        float ax = 0.f, ay = 0.f;
        int   cur = -1;
        for (int k = lo; k < hi; k++) {
            int   pos  = idx[k] & 31;         // position within thread's 32 slots
            int   cell = pos >> 1;
            float v    = urow[k] * SCALE_F;
            if (cell != cur) {
                if (cur >= 0) zb[obase ^ cur] = __floats2half2_rn(ax, ay);
                ax = 0.f; ay = 0.f; cur = cell;
            }
            if (pos & 1) ay += v; else ax += v;
        }
        if (cur >= 0) zb[obase ^ cur] = __floats2half2_rn(ax, ay);
    }
    // NO barrier: phase A reads only this thread's own cells.

    float2 x[16];

    // ---- R1: x[q] = elements (32t+2q, 32t+2q+1) ----
#pragma unroll
    for (int q = 0; q < 16; q++)
        x[q] = __half22float2(zb[obase ^ q]);

    // ---- phase A: bits 4:1 packed, bit0 scalar ----
#pragma unroll
    for (int s = 1; s < 16; s <<= 1)
#pragma unroll
        for (int i = 0; i < 16; i++)
            if ((i & s) == 0) {
                float2 a = x[i], b = x[i + s];
                x[i]     = fadd2(a, b);
                x[i + s] = ffma2(b, NEG1, a);
            }
#pragma unroll
    for (int i = 0; i < 16; i++) {
        float a = x[i].x, b = x[i].y;
        x[i].x = a + b;  x[i].y = a - b;
    }

    // ---- W2 -> tb: x[m] is already the bit0 half2 pair ----
#pragma unroll
    for (int m = 0; m < 16; m++)
        tb[obase ^ m] = __floats2half2_rn(x[m].x, x[m].y);
    __syncthreads();                       // B1

    // ---- R2: x[j] = pair at {bits12:9 = t>>4, bits8:5 = j, bits4:1 = t&15} ----
#pragma unroll
    for (int j = 0; j < 16; j++)
        x[j] = __half22float2(tb[rbase2 ^ (j * 17)]);   // j*17 = (j<<4)|j

    // ---- phase B: bits 8:5 packed (bit0 passenger) ----
#pragma unroll
    for (int s = 1; s < 16; s <<= 1)
#pragma unroll
        for (int i = 0; i < 16; i++)
            if ((i & s) == 0) {
                float2 a = x[i], b = x[i + s];
                x[i]     = fadd2(a, b);
                x[i + s] = ffma2(b, NEG1, a);
            }

    // ---- W3 -> zb (free after R1; ordered vs other threads' R1 by B1) ----
#pragma unroll
    for (int j = 0; j < 16; j++)
        zb[rbase2 ^ (j * 17)] = __floats2half2_rn(x[j].x, x[j].y);
    __syncthreads();                       // B2

    // ---- R3: x[g] = pair at {bits12:9 = g, bits8:1 = t} ----
#pragma unroll
    for (int g = 0; g < 16; g++)
        x[g] = __half22float2(zb[(g << 8) ^ ((g & 1) << 4) ^ r3base]);

    // ---- phase C: bits 12:9 packed (bit0 passenger) ----
#pragma unroll
    for (int s = 1; s < 16; s <<= 1)
#pragma unroll
        for (int i = 0; i < 16; i++)
            if ((i & s) == 0) {
                float2 a = x[i], b = x[i + s];
                x[i]     = fadd2(a, b);
                x[i + s] = ffma2(b, NEG1, a);
            }

    // ---- epilogue: 16 x STG.64, 256B contiguous per warp instruction ----
    float2* orow2 = reinterpret_cast<float2*>(out + (size_t)row * D_DIM);
#pragma unroll
    for (int g = 0; g < 16; g++)
        orow2[(g << 8) + t] = x[g];
}

extern "C" void kernel_launch(void* const* d_in, const int* in_sizes, int n_in,
                              void* d_out, int out_size)
{
    const float* u   = (const float*)d_in[0];
    const int*   idx = (const int*)d_in[1];
    float*       out = (float*)d_out;

    precompute_bounds<<<1, NT + 1>>>(idx);
    const int rows = in_sizes[0] / K_DIM;   // 8192
    fwht_up_kernel<<<rows, NT>>>(u, idx, out);
}